// round 16
// baseline (speedup 1.0000x reference)
#include <cuda_runtime.h>
#include <math.h>

// ============================================================================
// QModel 18-wire, batch 64. R12: 16 amps/thread, 2^12 tiles (32KB smem),
// launch_bounds(256,4) -> 32 warps/SM (was 16). f32x2 packed butterflies kept.
//
// wire w <-> bit (17-w). Per layer: 1q M=RY*RX on all bits, then CNOT chain
// CN(17,16),...,CN(1,0),CN(0,17).
//
// pass_hi: local {g0..4, g11..17}, tg(6)=g5..10
//   s1 reg {g14..17}: 1q(g14..17), CN(17,16),(16,15),(15,14)
//   s2 reg {g11..14}: 1q(g11..13), CN(14,13),(13,12),(12,11)
// pass_lo: local {g0..10, g17}, tg(6)=g11..16
//   s1 reg {g7..10}:  1q(g7..10), csw CN(11,10) on tg0, CN(10,9),(9,8),(8,7)
//   s2 reg {g3..6}:   1q(g3..6),  csw CN(7,6) on thr L7, CN(6,5),(5,4),(4,3)
//   s3 reg {g0,g1,g2,g17}: 1q(g0..2), csw CN(3,2) on thr L3,
//                          CN(2,1),(1,0),CN(0,17)=cnot<0,3>
// ============================================================================

typedef unsigned long long u64;

__device__ u64  g_state[1 << 24];          // 128 MB packed complex scratch
__device__ float g_partial[4096 * 18];     // per-tile signed-prob partials

// ---- packed f32x2 helpers --------------------------------------------------
__device__ __forceinline__ u64 pk2(float lo, float hi) {
    u64 r; asm("mov.b64 %0, {%1, %2};" : "=l"(r) : "f"(lo), "f"(hi)); return r;
}
__device__ __forceinline__ u64 swp(u64 v) {          // (r,i) -> (i,r)
    unsigned lo, hi;
    asm("mov.b64 {%0, %1}, %2;" : "=r"(lo), "=r"(hi) : "l"(v));
    u64 r; asm("mov.b64 %0, {%1, %2};" : "=l"(r) : "r"(hi), "r"(lo));
    return r;
}
__device__ __forceinline__ u64 mul2(u64 a, u64 b) {
    u64 r; asm("mul.rn.f32x2 %0, %1, %2;" : "=l"(r) : "l"(a), "l"(b)); return r;
}
__device__ __forceinline__ u64 fma2(u64 a, u64 b, u64 c) {
    u64 r; asm("fma.rn.f32x2 %0, %1, %2, %3;" : "=l"(r) : "l"(a), "l"(b), "l"(c));
    return r;
}
__device__ __forceinline__ void upk(u64 v, float &lo, float &hi) {
    asm("mov.b64 {%0, %1}, %2;" : "=f"(lo), "=f"(hi) : "l"(v));
}

// M = RY*RX (A=c^2, B=s^2, D=cs):
//   n0 = (A,A)*v0 + (-B,B)*v0s + (-D,-D)*v1 + (D,-D)*v1s
//   n1 = (D,D)*v0 + (D,-D)*v0s + (A,A)*v1  + (B,-B)*v1s
struct Coef { u64 AA, mBB, mDmD, DmD, DD, BmB; };

__device__ __forceinline__ Coef mkcoef(float cA, float cB, float cD) {
    Coef K;
    K.AA   = pk2(cA, cA);
    K.mBB  = pk2(-cB, cB);
    K.mDmD = pk2(-cD, -cD);
    K.DmD  = pk2(cD, -cD);
    K.DD   = pk2(cD, cD);
    K.BmB  = pk2(cB, -cB);
    return K;
}

__device__ __forceinline__ void u2(u64 &x0, u64 &x1, const Coef &K) {
    u64 v0 = x0, v1 = x1;
    u64 v0s = swp(v0), v1s = swp(v1);
    u64 n0 = mul2(K.AA, v0);
    n0 = fma2(K.mBB, v0s, n0);
    n0 = fma2(K.mDmD, v1, n0);
    n0 = fma2(K.DmD, v1s, n0);
    u64 n1 = mul2(K.DD, v0);
    n1 = fma2(K.DmD, v0s, n1);
    n1 = fma2(K.AA, v1, n1);
    n1 = fma2(K.BmB, v1s, n1);
    x0 = n0; x1 = n1;
}

template <int B>
__device__ __forceinline__ void apply1q(u64 a[16], const Coef &K) {
#pragma unroll
    for (int i = 0; i < 16; i++)
        if ((i & (1 << B)) == 0)
            u2(a[i], a[i | (1 << B)], K);
}

template <int C, int T>
__device__ __forceinline__ void cnot(u64 a[16]) {
#pragma unroll
    for (int i = 0; i < 16; i++)
        if ((i & (1 << C)) && !(i & (1 << T))) {
            u64 tmp = a[i]; a[i] = a[i | (1 << T)]; a[i | (1 << T)] = tmp;
        }
}

template <int T>
__device__ __forceinline__ void condswap(u64 a[16], int cond) {
    if (cond) {
#pragma unroll
        for (int i = 0; i < 16; i++)
            if (!(i & (1 << T))) {
                u64 tmp = a[i]; a[i] = a[i | (1 << T)]; a[i | (1 << T)] = tmp;
            }
    }
}

// pass_lo exchange-1 swizzle: fold L7 into bank bit 3.
__device__ __forceinline__ int SW1(int L) { return L ^ (((L >> 7) & 1) << 3); }
// pass_lo exchange-2 swizzle: fold L3..6 into bank bits 0..3, plus L7 into bit 3.
__device__ __forceinline__ int SW2x(int L) {
    return L ^ ((L >> 3) & 15) ^ (((L >> 7) & 1) << 3);
}

// ---------------------------------------------------------------------------
// pass_hi: local {g0..4, g11..17}; tg(6 bits) = g5..10.
// L0..4=g0..4, L5=g11, L6=g12, L7=g13, L8..11=g14..17.
// s1: thread t0..4->L0..4, t5..7->L5..7; reg r->L8..11.
// s2: reg r0..3 -> L5..8 (g11..14); thread t0..4->L0..4, t5..7->L9..11.
// ---------------------------------------------------------------------------
__global__ void __launch_bounds__(256, 4)
pass_hi(const float* __restrict__ in_re, const float* __restrict__ in_im,
        int first, float cA, float cB, float cD) {
    extern __shared__ u64 sm[];
    const Coef K = mkcoef(cA, cB, cD);
    int t = threadIdx.x;
    int blk = blockIdx.x;
    int tg = blk & 63;
    int base = ((blk >> 6) << 18) | (tg << 5);
    u64 a[16];

    // s1 load: g = base | t0..4 | (t5..7 -> g11..13) | (r -> g14..17)
    int toff = (t & 31) | (((t >> 5) & 7) << 11);
    if (first) {
#pragma unroll
        for (int r = 0; r < 16; r++) {
            int g = base + toff + (r << 14);
            a[r] = pk2(in_re[g], in_im[g]);
        }
    } else {
#pragma unroll
        for (int r = 0; r < 16; r++)
            a[r] = g_state[base + toff + (r << 14)];
    }
    apply1q<0>(a, K);   // g14
    apply1q<1>(a, K);   // g15
    apply1q<2>(a, K);   // g16
    apply1q<3>(a, K);   // g17
    cnot<3, 2>(a);      // CN(17,16)
    cnot<2, 1>(a);      // CN(16,15)
    cnot<1, 0>(a);      // CN(15,14)

    // exchange (identity layout; both sides have bank bits = t0..3)
#pragma unroll
    for (int r = 0; r < 16; r++) sm[t | (r << 8)] = a[r];
    __syncthreads();

    // s2 read: L = t0..4 | (r<<5) | (t5..7 <<9)
    int tb = (t & 31) | ((t >> 5) << 9);
#pragma unroll
    for (int r = 0; r < 16; r++)
        a[r] = sm[tb | (r << 5)];

    apply1q<0>(a, K);   // g11
    apply1q<1>(a, K);   // g12
    apply1q<2>(a, K);   // g13
    cnot<3, 2>(a);      // CN(14,13)
    cnot<2, 1>(a);      // CN(13,12)
    cnot<1, 0>(a);      // CN(12,11)

    // store: g = base | t0..4 | (r0..2 -> g11..13) | (r3 -> g14) | (t5..7 -> g15..17)
    int sbase = base + (t & 31) + (((t >> 5) & 7) << 15);
#pragma unroll
    for (int r = 0; r < 16; r++) {
        int g = sbase + ((r & 7) << 11) + (((r >> 3) & 1) << 14);
        g_state[g] = a[r];
    }
}

// ---------------------------------------------------------------------------
// pass_lo: local {g0..10, g17}; tg(6 bits) = g11..16.
// L0..10=g0..10, L11=g17.
// s1: thread t0..6->L0..6, t7->L11; reg r->L7..10 (g7..10).
// s2: thread t0..2->L0..2, t3..7->L7..11; reg r->L3..6 (g3..6).
// s3: thread t0..7->L3..10; reg r0..2->L0..2 (g0..2), r3->L11 (g17).
// ---------------------------------------------------------------------------
__global__ void __launch_bounds__(256, 4)
pass_lo(int measure, float cA, float cB, float cD) {
    extern __shared__ u64 sm[];
    const Coef K = mkcoef(cA, cB, cD);
    int t = threadIdx.x;
    int blk = blockIdx.x;
    int tg = blk & 63;
    int base = ((blk >> 6) << 18) | (tg << 11);
    u64 a[16];

    // s1 load: g = base | t0..6 | (t7 -> g17) | (r -> g7..10)
    int toff = (t & 127) | (((t >> 7) & 1) << 17);
#pragma unroll
    for (int r = 0; r < 16; r++)
        a[r] = g_state[base + toff + (r << 7)];

    apply1q<0>(a, K);       // g7
    apply1q<1>(a, K);       // g8
    apply1q<2>(a, K);       // g9
    apply1q<3>(a, K);       // g10
    condswap<3>(a, tg & 1); // CN(11,10): ctl g11 = tg bit0
    cnot<3, 2>(a);          // CN(10,9)
    cnot<2, 1>(a);          // CN(9,8)
    cnot<1, 0>(a);          // CN(8,7)

    // exchange 1 (SW1): write L = t0..6 | (r<<7) | (t7<<11)
    int lw1 = (t & 127) | (((t >> 7) & 1) << 11);
#pragma unroll
    for (int r = 0; r < 16; r++) sm[SW1(lw1 | (r << 7))] = a[r];
    __syncthreads();

    // s2 read: L = t0..2 | (r<<3) | (t3..7 <<7)
    int tb2 = (t & 7) | ((t >> 3) << 7);
#pragma unroll
    for (int r = 0; r < 16; r++)
        a[r] = sm[SW1(tb2 | (r << 3))];

    apply1q<0>(a, K);              // g3
    apply1q<1>(a, K);              // g4
    apply1q<2>(a, K);              // g5
    apply1q<3>(a, K);              // g6
    condswap<3>(a, (t >> 3) & 1);  // CN(7,6): ctl g7 = thread L7
    cnot<3, 2>(a);                 // CN(6,5)
    cnot<2, 1>(a);                 // CN(5,4)
    cnot<1, 0>(a);                 // CN(4,3)

    __syncthreads();               // SW1-layout reads done before SW2x refill

    // exchange 2 (SW2x): same logical slots, new layout
#pragma unroll
    for (int r = 0; r < 16; r++) sm[SW2x(tb2 | (r << 3))] = a[r];
    __syncthreads();

    // s3 read: L = r0..2 | (t<<3) | (r3<<11)
#pragma unroll
    for (int r = 0; r < 16; r++)
        a[r] = sm[SW2x((r & 7) | (t << 3) | (((r >> 3) & 1) << 11))];

    apply1q<0>(a, K);          // g0
    apply1q<1>(a, K);          // g1
    apply1q<2>(a, K);          // g2
    condswap<2>(a, t & 1);     // CN(3,2): ctl g3 = thread L3
    cnot<2, 1>(a);             // CN(2,1)
    cnot<1, 0>(a);             // CN(1,0)
    cnot<0, 3>(a);             // CN(0,17): ctl g0=r0, tgt g17=r3

    if (!measure) {
        // store: g = base + (r&7) + (t<<3) + (r3<<17); 16B vectorized
#pragma unroll
        for (int h = 0; h < 2; h++) {
            u64* p = &g_state[base + (t << 3) + (h << 17)];
#pragma unroll
            for (int k = 0; k < 8; k += 2) {
                ulonglong2 v;
                v.x = a[h * 8 + k];
                v.y = a[h * 8 + k + 1];
                *reinterpret_cast<ulonglong2*>(p + k) = v;
            }
        }
    } else {
        // <Z>: varying bits: r0..2 -> g0..2, r3 -> g17; t -> g3..10; tg -> g11..16
        float pt = 0.f, s0 = 0.f, s1 = 0.f, s2 = 0.f, s17 = 0.f;
#pragma unroll
        for (int r = 0; r < 16; r++) {
            float xr, xi;
            upk(a[r], xr, xi);
            float p = xr * xr + xi * xi;
            pt += p;
            s0  += (r & 1) ? -p : p;
            s1  += (r & 2) ? -p : p;
            s2  += (r & 4) ? -p : p;
            s17 += (r & 8) ? -p : p;
        }
        float zb[18];
        zb[0] = s0; zb[1] = s1; zb[2] = s2; zb[17] = s17;
#pragma unroll
        for (int k = 0; k < 8; k++) zb[3 + k] = ((t >> k) & 1) ? -pt : pt;   // g3..10
#pragma unroll
        for (int k = 0; k < 6; k++) zb[11 + k] = ((tg >> k) & 1) ? -pt : pt; // g11..16

        __syncthreads();  // tile reads done; reuse smem for reduction
        float* red = (float*)sm;
        int lane = t & 31, warp = t >> 5;
#pragma unroll
        for (int b = 0; b < 18; b++) {
            float v = zb[b];
            v += __shfl_down_sync(0xffffffffu, v, 16);
            v += __shfl_down_sync(0xffffffffu, v, 8);
            v += __shfl_down_sync(0xffffffffu, v, 4);
            v += __shfl_down_sync(0xffffffffu, v, 2);
            v += __shfl_down_sync(0xffffffffu, v, 1);
            if (lane == 0) red[warp * 18 + b] = v;
        }
        __syncthreads();
        if (t < 18) {
            float v = 0.f;
#pragma unroll
            for (int w = 0; w < 8; w++) v += red[w * 18 + t];
            g_partial[blk * 18 + (17 - t)] = v;  // wire = 17 - bit
        }
    }
}

// ---------------------------------------------------------------------------
// head: out[b] = sum_w feats[b,w]*hw[w] + hb  (deterministic partial sum)
// ---------------------------------------------------------------------------
__global__ void head_k(const float* __restrict__ hw, const float* __restrict__ hb,
                       float* __restrict__ out) {
    int b = blockIdx.x;
    int w = threadIdx.x;
    float v = 0.f;
    if (w < 18) {
#pragma unroll
        for (int tile = 0; tile < 64; tile++)
            v += g_partial[(b * 64 + tile) * 18 + w];
        v *= hw[w];
    }
    v += __shfl_down_sync(0xffffffffu, v, 16);
    v += __shfl_down_sync(0xffffffffu, v, 8);
    v += __shfl_down_sync(0xffffffffu, v, 4);
    v += __shfl_down_sync(0xffffffffu, v, 2);
    v += __shfl_down_sync(0xffffffffu, v, 1);
    if (w == 0) out[b] = v + hb[0];
}

extern "C" void kernel_launch(void* const* d_in, const int* in_sizes, int n_in,
                              void* d_out, int out_size) {
    const float* re = (const float*)d_in[0];
    const float* im = (const float*)d_in[1];
    const float* hw = (const float*)d_in[2];
    const float* hb = (const float*)d_in[3];
    float* out = (float*)d_out;

    const double th = 0.1;
    const double c = cos(th * 0.5), s = sin(th * 0.5);
    const float cA = (float)(c * c), cB = (float)(s * s), cD = (float)(c * s);

    const int SMEM = (1 << 12) * sizeof(u64);  // 32 KB
    cudaFuncSetAttribute(pass_hi, cudaFuncAttributeMaxDynamicSharedMemorySize, SMEM);
    cudaFuncSetAttribute(pass_lo, cudaFuncAttributeMaxDynamicSharedMemorySize, SMEM);

    for (int layer = 0; layer < 3; layer++) {
        pass_hi<<<4096, 256, SMEM>>>(re, im, layer == 0 ? 1 : 0, cA, cB, cD);
        pass_lo<<<4096, 256, SMEM>>>(layer == 2 ? 1 : 0, cA, cB, cD);
    }
    head_k<<<64, 32>>>(hw, hb, out);
}